// round 11
// baseline (speedup 1.0000x reference)
#include <cuda_runtime.h>

// Problem constants (fixed by reference: (3,x)-regular-column LDPC)
#define N_VAR  1152
#define M_CHK  576
#define E_EDGE 3456   // N_VAR * 3
#define BATCH  16
#define MAXD   32     // max co-check neighbors per edge
#define CLUSTER_CTAS 8
#define EDGES_PER_CTA (E_EDGE / CLUSTER_CTAS)   // 432
#define VARS_PER_CTA  (N_VAR / CLUSTER_CTAS)    // 144

// Scratch (no allocation) — fully re-derived every launch (graph-replay safe).
__device__ int    g_p_r2l[E_EDGE];        // col-major edge -> row-major index (ascending per var)
__device__ int    g_p_l2r[E_EDGE];        // inverse permutation
__device__ int    g_adj[E_EDGE * MAXD];   // row-major edge -> co-check col-major edges (ascending)
__device__ int    g_deg[E_EDGE];
__device__ int    g_sel_y;                // 1 if en1 is H_xe_v_sumc_to_y
__device__ float2 g_lrk[BATCH * E_EDGE];  // per col-major edge: {log-mag, k-sign}
__device__ float  g_vsr[BATCH * E_EDGE];  // per row-major edge: C->V message

// ---------------------------------------------------------------------------
// Kernel 1: classify the two [E*N] inputs. H_x_to_xe0[e, e/3]==1 for ALL e.
// Single block, exhaustive (3456 probes per matrix).
// ---------------------------------------------------------------------------
__global__ void probe_en_kernel(const float* __restrict__ en0,
                                const float* __restrict__ en1) {
    __shared__ int w0[32], w1[32];
    int tid = threadIdx.x;
    int c0 = 0, c1 = 0;
    for (int e = tid; e < E_EDGE; e += 1024) {
        size_t off = (size_t)e * N_VAR + e / 3;
        c0 += (en0[off] == 1.0f) ? 1 : 0;
        c1 += (en1[off] == 1.0f) ? 1 : 0;
    }
    for (int o = 16; o > 0; o >>= 1) {
        c0 += __shfl_down_sync(0xffffffff, c0, o);
        c1 += __shfl_down_sync(0xffffffff, c1, o);
    }
    if ((tid & 31) == 0) { w0[tid >> 5] = c0; w1[tid >> 5] = c1; }
    __syncthreads();
    if (tid == 0) {
        int t0 = 0, t1 = 0;
        for (int w = 0; w < 32; ++w) { t0 += w0[w]; t1 += w1[w]; }
        // the matrix passing for all e is H_x_to_xe0; the OTHER is Hy
        g_sel_y = (t1 == E_EDGE && t0 != E_EDGE) ? 0 : 1;
    }
}

// ---------------------------------------------------------------------------
// Kernel 2: extract p_r2l / p_l2r from H_xe_v_sumc_to_y [N_VAR, E].
// Row v has exactly 3 ones at ascending columns = p_r2l[3v..3v+2]
// (within a column, ascending check row => ascending row-major index).
// ---------------------------------------------------------------------------
__global__ void extract_perm_kernel(const float* __restrict__ en0,
                                    const float* __restrict__ en1) {
    const float* Hy = g_sel_y ? en1 : en0;
    int v = blockIdx.x;
    __shared__ int idxs[8];
    __shared__ int cnt;
    if (threadIdx.x == 0) { cnt = 0; idxs[0] = 0; idxs[1] = 0; idxs[2] = 0; }
    __syncthreads();

    const float4* row = reinterpret_cast<const float4*>(Hy + (size_t)v * E_EDGE);
    for (int q = threadIdx.x; q < E_EDGE / 4; q += blockDim.x) {
        float4 f = row[q];
        if (f.x != 0.0f) { int p = atomicAdd(&cnt, 1); if (p < 8) idxs[p] = 4 * q + 0; }
        if (f.y != 0.0f) { int p = atomicAdd(&cnt, 1); if (p < 8) idxs[p] = 4 * q + 1; }
        if (f.z != 0.0f) { int p = atomicAdd(&cnt, 1); if (p < 8) idxs[p] = 4 * q + 2; }
        if (f.w != 0.0f) { int p = atomicAdd(&cnt, 1); if (p < 8) idxs[p] = 4 * q + 3; }
    }
    __syncthreads();
    if (threadIdx.x == 0) {
        int a = idxs[0], b = idxs[1], c = idxs[2], t;
        if (a > b) { t = a; a = b; b = t; }
        if (b > c) { t = b; b = c; c = t; }
        if (a > b) { t = a; a = b; b = t; }
        g_p_r2l[3 * v + 0] = a;  g_p_l2r[a] = 3 * v + 0;
        g_p_r2l[3 * v + 1] = b;  g_p_l2r[b] = 3 * v + 1;
        g_p_r2l[3 * v + 2] = c;  g_p_l2r[c] = 3 * v + 2;
    }
}

// ---------------------------------------------------------------------------
// Kernel 3: check groups + adjacency WITHOUT the 48 MB scan.
// np.nonzero is row-major => edges of a check are CONTIGUOUS in row-major
// order. Probe H_sumC_to_V[j-1, p_l2r[j]] (==S_C[j-1,j]) for all j:
//   1 => same check as previous edge; 0 => new group.
// The same probes classify the EE pair: the true C2V yields ~E-M ones,
// the V2C matrix ~0. Then scan group starts and, per group, emit the
// ascending-sorted adjacency minus self (identical to the passing R10 adj).
// Single block of 1024 threads.
// ---------------------------------------------------------------------------
__global__ void build_groups_kernel(const float* __restrict__ ee0,
                                    const float* __restrict__ ee1) {
    __shared__ unsigned char f0[E_EDGE], f1[E_EDGE];
    __shared__ int tsum[1024];
    __shared__ int cs[M_CHK + 1];
    __shared__ int w0[32], w1[32];
    __shared__ int sel_c2v, ngroups;
    int tid = threadIdx.x;

    // probe both matrices
    int c0 = 0, c1 = 0;
    for (int j = tid; j < E_EDGE; j += 1024) {
        int p0 = 0, p1 = 0;
        if (j > 0) {
            size_t off = (size_t)(j - 1) * E_EDGE + g_p_l2r[j];
            p0 = (ee0[off] != 0.0f) ? 1 : 0;
            p1 = (ee1[off] != 0.0f) ? 1 : 0;
        }
        f0[j] = (unsigned char)p0;
        f1[j] = (unsigned char)p1;
        c0 += p0; c1 += p1;
    }
    for (int o = 16; o > 0; o >>= 1) {
        c0 += __shfl_down_sync(0xffffffff, c0, o);
        c1 += __shfl_down_sync(0xffffffff, c1, o);
    }
    if ((tid & 31) == 0) { w0[tid >> 5] = c0; w1[tid >> 5] = c1; }
    __syncthreads();
    if (tid == 0) {
        int t0 = 0, t1 = 0;
        for (int w = 0; w < 32; ++w) { t0 += w0[w]; t1 += w1[w]; }
        sel_c2v = (t1 > t0) ? 1 : 0;   // more same-check hits => that one is C2V
    }
    __syncthreads();
    const unsigned char* f = sel_c2v ? f1 : f0;

    // local scan of "new group" flags (4 per thread)
    int base = tid * 4;
    int loc[4], s = 0;
    #pragma unroll
    for (int m = 0; m < 4; ++m) {
        int j = base + m;
        int v = 0;
        if (j < E_EDGE) v = (j == 0) ? 1 : (f[j] ? 0 : 1);
        loc[m] = v; s += v;
    }
    tsum[tid] = s;
    __syncthreads();
    for (int off = 1; off < 1024; off <<= 1) {
        int add = (tid >= off) ? tsum[tid - off] : 0;
        __syncthreads();
        tsum[tid] += add;
        __syncthreads();
    }
    int run = (tid == 0) ? 0 : tsum[tid - 1];

    if (tid <= M_CHK) cs[tid] = E_EDGE;     // default (incl. sentinel end)
    __syncthreads();
    #pragma unroll
    for (int m = 0; m < 4; ++m) {
        int j = base + m;
        if (j < E_EDGE && loc[m]) {
            if (run <= M_CHK) cs[run] = j;  // group `run` starts at j
            ++run;
        }
    }
    if (tid == 0) {
        int n = tsum[1023];
        ngroups = (n > M_CHK) ? M_CHK : n;
    }
    __syncthreads();

    // per-group: sort member col-major indices ascending, write per-member
    // adjacency excluding self (matches R10's sorted direct-sum order).
    for (int g = tid; g < ngroups; g += 1024) {
        int s0 = cs[g], e0 = cs[g + 1];
        int d = e0 - s0;
        if (d > MAXD) d = MAXD;
        int cols[MAXD];
        for (int i = 0; i < d; ++i) cols[i] = g_p_l2r[s0 + i];
        for (int i = 1; i < d; ++i) {
            int key = cols[i], q = i - 1;
            while (q >= 0 && cols[q] > key) { cols[q + 1] = cols[q]; --q; }
            cols[q + 1] = key;
        }
        for (int i = 0; i < d; ++i) {
            int j = s0 + i;                 // row-major member
            int own = g_p_l2r[j];
            g_deg[j] = d - 1;
            int* dst = g_adj + (size_t)j * MAXD;
            int w = 0;
            for (int q = 0; q < d; ++q)
                if (cols[q] != own) dst[w++] = cols[q];
        }
    }
}

// ---------------------------------------------------------------------------
// Helpers
// ---------------------------------------------------------------------------
__device__ __forceinline__ float2 lrk_of(float x) {
    float t = tanhf(0.5f * x);
    float lr = logf(1e-8f + fabsf(t));
    float k = (x < 0.0f) ? 2.0f : ((x > 0.0f) ? 0.0f : 1.0f);
    return make_float2(lr, k);
}

__device__ __forceinline__ void cluster_sync_() {
    asm volatile("barrier.cluster.arrive.aligned;" ::: "memory");
    asm volatile("barrier.cluster.wait.aligned;" ::: "memory");
}

// ---------------------------------------------------------------------------
// Kernel 4: FUSED BP. 16 clusters (one per batch item) x 8 CTAs x 256 thr.
// All iterations in one kernel; phase sync = cluster barrier (+ gpu fence).
// Cross-CTA message traffic via L2 (__ldcg bypasses L1; global stores are
// write-through to L2). Arithmetic identical to the passing R10 kernel.
// ---------------------------------------------------------------------------
__global__ void __cluster_dims__(CLUSTER_CTAS, 1, 1) __launch_bounds__(256, 1)
bp_fused_kernel(const float* __restrict__ llr_in,
                const int* __restrict__ iters_p,
                float* __restrict__ out) {
    const int b    = blockIdx.x / CLUSTER_CTAS;   // batch item
    const int rank = blockIdx.x % CLUSTER_CTAS;
    const int tid  = threadIdx.x;
    const int e0   = rank * EDGES_PER_CTA;

    int iters = iters_p ? iters_p[0] : 8;
    if (iters < 1 || iters > 64) iters = 8;

    const float* llrb = llr_in + b * N_VAR;
    float2* lrk = g_lrk + (size_t)b * E_EDGE;
    float*  vsr = g_vsr + (size_t)b * E_EDGE;

    // init: v2c(0) = llr of own variable -> lrk
    for (int c = e0 + tid; c < e0 + EDGES_PER_CTA; c += 256)
        lrk[c] = lrk_of(__ldg(&llrb[c / 3]));
    __threadfence();
    cluster_sync_();

    for (int it = 0; it < iters; ++it) {
        // ---- check->variable (per row-major edge, ascending neighbor sums) ----
        for (int a = e0 + tid; a < e0 + EDGES_PER_CTA; a += 256) {
            int n = g_deg[a];
            const int* ad = g_adj + (size_t)a * MAXD;
            float slr = 0.0f, skf = 0.0f;
            for (int i = 0; i < n; ++i) {
                float2 lk = __ldcg(&lrk[ad[i]]);
                slr += lk.x;
                skf += lk.y;
            }
            int sk = (int)skf;   // exact small integer
            // cos(sk*pi/2): exactly +-1 for even sk, 0 for odd
            float cv = (sk & 1) ? 0.0f : ((sk & 2) ? -1.0f : 1.0f);
            float prod = expf(slr) * cv;
            float s = (prod > 0.0f) ? 1.0f : ((prod < 0.0f) ? -1.0f : 0.0f);
            float pd = prod - 2e-7f * s;
            vsr[a] = logf((1.0f + pd) / (1.0f - pd + 1e-10f));
        }
        __threadfence();
        cluster_sync_();

        if (it < iters - 1) {
            // ---- variable->check fused with next-iteration log-magnitude ----
            for (int c = e0 + tid; c < e0 + EDGES_PER_CTA; c += 256) {
                int v = c / 3, base = 3 * v, r = c - base;
                int j1 = g_p_r2l[base + ((r == 0) ? 1 : 0)];
                int j2 = g_p_r2l[base + ((r == 2) ? 1 : 2)];
                float x = __ldg(&llrb[v]) + (__ldcg(&vsr[j1]) + __ldcg(&vsr[j2]));
                lrk[c] = lrk_of(x);
            }
            __threadfence();
            cluster_sync_();
        }
    }

    // ---- hard decision (float 0/1 output — dtype lesson of round 9) ----
    for (int v = rank * VARS_PER_CTA + tid; v < (rank + 1) * VARS_PER_CTA; v += 256) {
        int base = 3 * v;
        float T = (__ldcg(&vsr[g_p_r2l[base]]) + __ldcg(&vsr[g_p_r2l[base + 1]]))
                  + __ldcg(&vsr[g_p_r2l[base + 2]]);
        float l = __ldg(&llrb[v]) + T;
        int sgn = (l > 0.0f) ? 1 : ((l < 0.0f) ? -1 : 0);
        out[b * N_VAR + v] = (float)((1 - sgn) >> 1);   // 0.0f or 1.0f
    }
}

// ---------------------------------------------------------------------------
// Inputs identified by element count (robust to ordering):
//   18432      -> llr_in [16,1152]
//   3981312 x2 -> H_x_to_xe0 [E,N] / H_xe_v_sumc_to_y [N,E]  (probed)
//   11943936x2 -> H_sumC_to_V / H_sumV_to_C [E,E]            (probed)
//   1          -> bp_iter_num int32
// Output: float32 [16, 1152] (0.0 / 1.0)
// ---------------------------------------------------------------------------
extern "C" void kernel_launch(void* const* d_in, const int* in_sizes, int n_in,
                              void* d_out, int out_size) {
    int idx_llr = -1, idx_it = -1;
    int en[2] = {-1, -1}, ee[2] = {-1, -1};
    int nen = 0, nee = 0;
    for (int i = 0; i < n_in; ++i) {
        int s = in_sizes[i];
        if (s == BATCH * N_VAR) idx_llr = i;
        else if (s == 1) idx_it = i;
        else if (s == E_EDGE * N_VAR) { if (nen < 2) en[nen] = i; nen++; }
        else if (s == E_EDGE * E_EDGE) { if (nee < 2) ee[nee] = i; nee++; }
    }
    if (idx_llr < 0) idx_llr = 0;
    if (en[0] < 0) en[0] = 1;
    if (en[1] < 0) en[1] = 4;
    if (ee[0] < 0) ee[0] = 2;
    if (ee[1] < 0) ee[1] = 3;

    const float* llr = (const float*)d_in[idx_llr];
    const float* en0 = (const float*)d_in[en[0]];
    const float* en1 = (const float*)d_in[en[1]];
    const float* ee0 = (const float*)d_in[ee[0]];
    const float* ee1 = (const float*)d_in[ee[1]];
    const int* iters = (idx_it >= 0) ? (const int*)d_in[idx_it] : (const int*)0;
    float* out = (float*)d_out;

    probe_en_kernel<<<1, 1024>>>(en0, en1);
    extract_perm_kernel<<<N_VAR, 128>>>(en0, en1);
    build_groups_kernel<<<1, 1024>>>(ee0, ee1);
    bp_fused_kernel<<<BATCH * CLUSTER_CTAS, 256>>>(llr, iters, out);
}